// round 11
// baseline (speedup 1.0000x reference)
#include <cuda_runtime.h>

// Problem constants
#define BB 4
#define TT 4
#define CC 128
#define NN 4096
#define HW 1024

typedef unsigned long long ull;

// ---------- f32x2 packed-math helpers (Blackwell FFMA2 path) ----------
__device__ __forceinline__ ull fma2(ull a, ull b, ull c) {
    ull d; asm("fma.rn.f32x2 %0, %1, %2, %3;" : "=l"(d) : "l"(a), "l"(b), "l"(c)); return d;
}
__device__ __forceinline__ ull mul2(ull a, ull b) {
    ull d; asm("mul.rn.f32x2 %0, %1, %2;" : "=l"(d) : "l"(a), "l"(b)); return d;
}
__device__ __forceinline__ ull pack2(float lo, float hi) {
    ull d; asm("mov.b64 %0, {%1, %2};" : "=l"(d) : "f"(lo), "f"(hi)); return d;
}
__device__ __forceinline__ void unpack2(ull a, float& lo, float& hi) {
    asm("mov.b64 {%0, %1}, %2;" : "=f"(lo), "=f"(hi) : "l"(a));
}

// ---------- device scratch (no allocations allowed) ----------
__device__ float g_Q[BB * NN * CC];
__device__ float g_K[BB * NN * CC];
__device__ float g_V[BB * NN * CC];
__device__ float g_O[BB * NN * CC];

// =====================================================================
// Kernel 1: input projections.  out[b][n][co] = sum_ci W[co][ci]*X + bias
//   sel==0: Q from spatial_features [B,T,C,H,W]  (gather, t fixed per tile)
//   sel==1: K from temporal        [B,C,T,H,W] == [B,C,N]
//   sel==2: V from temporal
// Output stored row-major [B][N][C].
// grid (32, 4), 256 threads, dyn smem = 2*128*132*4 bytes
// =====================================================================
__global__ __launch_bounds__(256) void proj_in_kernel(
    const float* __restrict__ X, const float* __restrict__ W,
    const float* __restrict__ bias, int sel)
{
    extern __shared__ float sm[];
    float* Wsm = sm;               // [128][132]  Wsm[ci][co] (transposed)
    float* Xsm = sm + 128 * 132;   // [128][132]  Xsm[ci][j]
    const int b = blockIdx.y;
    const int n0 = blockIdx.x * 128;
    const int tid = threadIdx.x;

    // Load W transposed into smem
    for (int idx = tid; idx < 128 * 128; idx += 256) {
        int co = idx >> 7, ci = idx & 127;
        Wsm[ci * 132 + co] = W[idx];
    }
    // Load X tile (128 ci x 128 n), vectorized
    if (sel == 0) {
        int t = n0 >> 10, hw0 = n0 & 1023;
        const float* src = X + ((size_t)(b * TT + t) * CC) * HW + hw0;
        for (int idx = tid; idx < 128 * 32; idx += 256) {
            int ci = idx >> 5, c4 = (idx & 31) * 4;
            *(float4*)&Xsm[ci * 132 + c4] = *(const float4*)&src[ci * HW + c4];
        }
    } else {
        const float* src = X + (size_t)b * CC * NN + n0;
        for (int idx = tid; idx < 128 * 32; idx += 256) {
            int ci = idx >> 5, c4 = (idx & 31) * 4;
            *(float4*)&Xsm[ci * 132 + c4] = *(const float4*)&src[ci * NN + c4];
        }
    }
    __syncthreads();

    const int tx = tid & 15, ty = tid >> 4;  // co-block = ty*8, n-block = tx*8
    ull acc[8][4];
#pragma unroll
    for (int i = 0; i < 8; i++)
#pragma unroll
        for (int jp = 0; jp < 4; jp++) acc[i][jp] = 0ull;

#pragma unroll 4
    for (int ci = 0; ci < 128; ci++) {
        const float4 w0 = *(const float4*)&Wsm[ci * 132 + ty * 8];
        const float4 w1 = *(const float4*)&Wsm[ci * 132 + ty * 8 + 4];
        const ulonglong2 xa = *(const ulonglong2*)&Xsm[ci * 132 + tx * 8];
        const ulonglong2 xb = *(const ulonglong2*)&Xsm[ci * 132 + tx * 8 + 4];
        float wv[8];
        wv[0] = w0.x; wv[1] = w0.y; wv[2] = w0.z; wv[3] = w0.w;
        wv[4] = w1.x; wv[5] = w1.y; wv[6] = w1.z; wv[7] = w1.w;
#pragma unroll
        for (int i = 0; i < 8; i++) {
            ull wd = pack2(wv[i], wv[i]);
            acc[i][0] = fma2(xa.x, wd, acc[i][0]);
            acc[i][1] = fma2(xa.y, wd, acc[i][1]);
            acc[i][2] = fma2(xb.x, wd, acc[i][2]);
            acc[i][3] = fma2(xb.y, wd, acc[i][3]);
        }
    }

    float* out = (sel == 0) ? g_Q : (sel == 1) ? g_K : g_V;
    float a[8][8];
#pragma unroll
    for (int i = 0; i < 8; i++) {
        float bi = bias[ty * 8 + i];
#pragma unroll
        for (int jp = 0; jp < 4; jp++) {
            float lo, hi; unpack2(acc[i][jp], lo, hi);
            a[i][2 * jp] = lo + bi; a[i][2 * jp + 1] = hi + bi;
        }
    }
#pragma unroll
    for (int j = 0; j < 8; j++) {
        float* dst = out + ((size_t)b * NN + n0 + tx * 8 + j) * CC + ty * 8;
        *(float4*)dst       = make_float4(a[0][j], a[1][j], a[2][j], a[3][j]);
        *(float4*)(dst + 4) = make_float4(a[4][j], a[5][j], a[6][j], a[7][j]);
    }
}

// =====================================================================
// Kernel 2: flash attention (fp32, f32x2 packed FMA).
//   grid (64, 4), 256 threads. BM=64 queries, BK=64 keys per tile.
//   smem: Qs[64][132], Ks[128][68] (transposed), Vs[64][132], Ps[64][68]
// =====================================================================
__global__ __launch_bounds__(256) void attn_kernel()
{
    extern __shared__ float sm[];
    float* Qs = sm;                       // 64*132
    float* Ks = Qs + 64 * 132;            // 128*68  Ks[c][key]
    float* Vs = Ks + 128 * 68;            // 64*132  Vs[key][c]
    float* Ps = Vs + 64 * 132;            // 64*68   Ps[row][key]

    const int b = blockIdx.y;
    const int m0 = blockIdx.x * 64;
    const int tid = threadIdx.x;
    const int tx = tid & 15, ty = tid >> 4;   // rows = ty*4.., key-cols = tx*4.., out-cols = tx*8..

    const float* Qg = g_Q + ((size_t)b * NN + m0) * CC;
    const float* Kg = g_K + (size_t)b * NN * CC;
    const float* Vg = g_V + (size_t)b * NN * CC;

    // Load Q tile (vectorized)
    for (int idx = tid; idx < 64 * 32; idx += 256) {
        int r = idx >> 5, c4 = (idx & 31) * 4;
        *(float4*)&Qs[r * 132 + c4] = *(const float4*)&Qg[r * 128 + c4];
    }

    float m_run[4], l_run[4];
    ull o2[4][4];
#pragma unroll
    for (int i = 0; i < 4; i++) {
        m_run[i] = -1e30f; l_run[i] = 0.f;
#pragma unroll
        for (int jp = 0; jp < 4; jp++) o2[i][jp] = 0ull;
    }

    const float scale = 0.08838834764831843f;  // 1/sqrt(128)

    for (int kt = 0; kt < 64; kt++) {
        __syncthreads();  // protects Ks/Vs/Ps reuse and (first iter) Qs
        const float* Kt = Kg + (size_t)kt * 64 * CC;
        const float* Vt = Vg + (size_t)kt * 64 * CC;
        // K: load float4, store transposed (scalar); V: float4 straight through
        for (int idx = tid; idx < 64 * 32; idx += 256) {
            int r = idx >> 5, c4 = (idx & 31) * 4;
            float4 kv = *(const float4*)&Kt[r * 128 + c4];
            Ks[(c4 + 0) * 68 + r] = kv.x;
            Ks[(c4 + 1) * 68 + r] = kv.y;
            Ks[(c4 + 2) * 68 + r] = kv.z;
            Ks[(c4 + 3) * 68 + r] = kv.w;
            *(float4*)&Vs[r * 132 + c4] = *(const float4*)&Vt[r * 128 + c4];
        }
        __syncthreads();

        // ---- S = Q K^T  (per-thread 4 rows x 4 key-cols) ----
        ull s2[4][2];
#pragma unroll
        for (int i = 0; i < 4; i++) { s2[i][0] = 0ull; s2[i][1] = 0ull; }

#pragma unroll 2
        for (int c = 0; c < 128; c += 4) {
            float qr[4][4];
#pragma unroll
            for (int i = 0; i < 4; i++) {
                float4 q = *(const float4*)&Qs[(ty * 4 + i) * 132 + c];
                qr[i][0] = q.x; qr[i][1] = q.y; qr[i][2] = q.z; qr[i][3] = q.w;
            }
            ulonglong2 kp[4];
#pragma unroll
            for (int cc = 0; cc < 4; cc++)
                kp[cc] = *(const ulonglong2*)&Ks[(c + cc) * 68 + tx * 4];
#pragma unroll
            for (int cc = 0; cc < 4; cc++) {
#pragma unroll
                for (int i = 0; i < 4; i++) {
                    ull qd = pack2(qr[i][cc], qr[i][cc]);
                    s2[i][0] = fma2(kp[cc].x, qd, s2[i][0]);
                    s2[i][1] = fma2(kp[cc].y, qd, s2[i][1]);
                }
            }
        }

        // ---- online softmax ----
        float s[4][4];
#pragma unroll
        for (int i = 0; i < 4; i++) {
            float l0, h0, l1, h1;
            unpack2(s2[i][0], l0, h0); unpack2(s2[i][1], l1, h1);
            s[i][0] = l0 * scale; s[i][1] = h0 * scale;
            s[i][2] = l1 * scale; s[i][3] = h1 * scale;
        }
#pragma unroll
        for (int i = 0; i < 4; i++) {
            float mt = fmaxf(fmaxf(s[i][0], s[i][1]), fmaxf(s[i][2], s[i][3]));
#pragma unroll
            for (int off = 1; off < 16; off <<= 1)
                mt = fmaxf(mt, __shfl_xor_sync(0xffffffffu, mt, off));
            float mnew = fmaxf(m_run[i], mt);
            float alpha = __expf(m_run[i] - mnew);
            m_run[i] = mnew;
            float rs = 0.f;
#pragma unroll
            for (int j = 0; j < 4; j++) { float p = __expf(s[i][j] - mnew); s[i][j] = p; rs += p; }
#pragma unroll
            for (int off = 1; off < 16; off <<= 1)
                rs += __shfl_xor_sync(0xffffffffu, rs, off);
            l_run[i] = l_run[i] * alpha + rs;
            ull ad = pack2(alpha, alpha);
#pragma unroll
            for (int jp = 0; jp < 4; jp++) o2[i][jp] = mul2(o2[i][jp], ad);
            *(float4*)&Ps[(ty * 4 + i) * 68 + tx * 4] =
                make_float4(s[i][0], s[i][1], s[i][2], s[i][3]);
        }
        __syncthreads();

        // ---- O += P V  (per-thread 4 rows x 8 c-cols) ----
#pragma unroll 2
        for (int k = 0; k < 64; k++) {
            ulonglong2 va = *(const ulonglong2*)&Vs[k * 132 + tx * 8];
            ulonglong2 vb = *(const ulonglong2*)&Vs[k * 132 + tx * 8 + 4];
#pragma unroll
            for (int i = 0; i < 4; i++) {
                float p = Ps[(ty * 4 + i) * 68 + k];
                ull pd = pack2(p, p);
                o2[i][0] = fma2(va.x, pd, o2[i][0]);
                o2[i][1] = fma2(va.y, pd, o2[i][1]);
                o2[i][2] = fma2(vb.x, pd, o2[i][2]);
                o2[i][3] = fma2(vb.y, pd, o2[i][3]);
            }
        }
    }

    // epilogue: O /= l, store [B][N][C]
#pragma unroll
    for (int i = 0; i < 4; i++) {
        float inv = 1.0f / l_run[i];
        float o[8];
#pragma unroll
        for (int jp = 0; jp < 4; jp++) unpack2(o2[i][jp], o[2 * jp], o[2 * jp + 1]);
        float* dst = g_O + ((size_t)b * NN + m0 + ty * 4 + i) * CC + tx * 8;
        *(float4*)dst       = make_float4(o[0] * inv, o[1] * inv, o[2] * inv, o[3] * inv);
        *(float4*)(dst + 4) = make_float4(o[4] * inv, o[5] * inv, o[6] * inv, o[7] * inv);
    }
}

// =====================================================================
// Kernel 3: output projection. out[b][co][n] = sum_c Wo[co][c]*O[b][n][c] + bo
// grid (32, 4), 256 threads, dyn smem = 2*128*132*4
// =====================================================================
__global__ __launch_bounds__(256) void proj_out_kernel(
    const float* __restrict__ W, const float* __restrict__ bias,
    float* __restrict__ out)
{
    extern __shared__ float sm[];
    float* Wsm = sm;               // [128][132]  Wsm[c][co]
    float* Xsm = sm + 128 * 132;   // [128][132]  Xsm[c][n]
    const int b = blockIdx.y;
    const int n0 = blockIdx.x * 128;
    const int tid = threadIdx.x;

    for (int idx = tid; idx < 128 * 128; idx += 256) {
        int co = idx >> 7, c = idx & 127;
        Wsm[c * 132 + co] = W[idx];
    }
    const float* src = g_O + ((size_t)b * NN + n0) * CC;
    for (int idx = tid; idx < 128 * 32; idx += 256) {
        int n = idx >> 5, c4 = (idx & 31) * 4;
        float4 v = *(const float4*)&src[n * CC + c4];
        Xsm[(c4 + 0) * 132 + n] = v.x;
        Xsm[(c4 + 1) * 132 + n] = v.y;
        Xsm[(c4 + 2) * 132 + n] = v.z;
        Xsm[(c4 + 3) * 132 + n] = v.w;
    }
    __syncthreads();

    const int tx = tid & 15, ty = tid >> 4;
    ull acc[8][4];
#pragma unroll
    for (int i = 0; i < 8; i++)
#pragma unroll
        for (int jp = 0; jp < 4; jp++) acc[i][jp] = 0ull;

#pragma unroll 4
    for (int c = 0; c < 128; c++) {
        const float4 w0 = *(const float4*)&Wsm[c * 132 + ty * 8];
        const float4 w1 = *(const float4*)&Wsm[c * 132 + ty * 8 + 4];
        const ulonglong2 xa = *(const ulonglong2*)&Xsm[c * 132 + tx * 8];
        const ulonglong2 xb = *(const ulonglong2*)&Xsm[c * 132 + tx * 8 + 4];
        float wv[8];
        wv[0] = w0.x; wv[1] = w0.y; wv[2] = w0.z; wv[3] = w0.w;
        wv[4] = w1.x; wv[5] = w1.y; wv[6] = w1.z; wv[7] = w1.w;
#pragma unroll
        for (int i = 0; i < 8; i++) {
            ull wd = pack2(wv[i], wv[i]);
            acc[i][0] = fma2(xa.x, wd, acc[i][0]);
            acc[i][1] = fma2(xa.y, wd, acc[i][1]);
            acc[i][2] = fma2(xb.x, wd, acc[i][2]);
            acc[i][3] = fma2(xb.y, wd, acc[i][3]);
        }
    }

    float a[8][8];
#pragma unroll
    for (int i = 0; i < 8; i++) {
        float bi = bias[ty * 8 + i];
#pragma unroll
        for (int jp = 0; jp < 4; jp++) {
            float lo, hi; unpack2(acc[i][jp], lo, hi);
            a[i][2 * jp] = lo + bi; a[i][2 * jp + 1] = hi + bi;
        }
    }
#pragma unroll
    for (int i = 0; i < 8; i++) {
        float* dst = out + ((size_t)b * CC + ty * 8 + i) * NN + n0 + tx * 8;
        *(float4*)dst       = make_float4(a[i][0], a[i][1], a[i][2], a[i][3]);
        *(float4*)(dst + 4) = make_float4(a[i][4], a[i][5], a[i][6], a[i][7]);
    }
}

// =====================================================================
extern "C" void kernel_launch(void* const* d_in, const int* in_sizes, int n_in,
                              void* d_out, int out_size)
{
    const float* spatial  = (const float*)d_in[0];
    const float* temporal = (const float*)d_in[1];
    const float* Wq = (const float*)d_in[2];
    const float* bq = (const float*)d_in[3];
    const float* Wk = (const float*)d_in[4];
    const float* bk = (const float*)d_in[5];
    const float* Wv = (const float*)d_in[6];
    const float* bv = (const float*)d_in[7];
    const float* Wo = (const float*)d_in[8];
    const float* bo = (const float*)d_in[9];
    float* out = (float*)d_out;

    const int smem_proj = 2 * 128 * 132 * 4;                            // 135168
    const int smem_attn = (64 * 132 + 128 * 68 + 64 * 132 + 64 * 68) * 4; // 119808

    cudaFuncSetAttribute(proj_in_kernel,  cudaFuncAttributeMaxDynamicSharedMemorySize, smem_proj);
    cudaFuncSetAttribute(proj_out_kernel, cudaFuncAttributeMaxDynamicSharedMemorySize, smem_proj);
    cudaFuncSetAttribute(attn_kernel,     cudaFuncAttributeMaxDynamicSharedMemorySize, smem_attn);

    dim3 gp(32, 4);
    proj_in_kernel<<<gp, 256, smem_proj>>>(spatial,  Wq, bq, 0);
    proj_in_kernel<<<gp, 256, smem_proj>>>(temporal, Wk, bk, 1);
    proj_in_kernel<<<gp, 256, smem_proj>>>(temporal, Wv, bv, 2);
    attn_kernel<<<dim3(64, 4), 256, smem_attn>>>();
    proj_out_kernel<<<gp, 256, smem_proj>>>(Wo, bo, out);
}

// round 12
// speedup vs baseline: 1.0027x; 1.0027x over previous
#include <cuda_runtime.h>

// Problem constants
#define BB 4
#define TT 4
#define CC 128
#define NN 4096
#define HW 1024

typedef unsigned long long ull;

// ---------- f32x2 packed-math helpers (Blackwell FFMA2 path) ----------
__device__ __forceinline__ ull fma2(ull a, ull b, ull c) {
    ull d; asm("fma.rn.f32x2 %0, %1, %2, %3;" : "=l"(d) : "l"(a), "l"(b), "l"(c)); return d;
}
__device__ __forceinline__ ull mul2(ull a, ull b) {
    ull d; asm("mul.rn.f32x2 %0, %1, %2;" : "=l"(d) : "l"(a), "l"(b)); return d;
}
__device__ __forceinline__ ull pack2(float lo, float hi) {
    ull d; asm("mov.b64 %0, {%1, %2};" : "=l"(d) : "f"(lo), "f"(hi)); return d;
}
__device__ __forceinline__ void unpack2(ull a, float& lo, float& hi) {
    asm("mov.b64 {%0, %1}, %2;" : "=f"(lo), "=f"(hi) : "l"(a));
}

// ---------- device scratch (no allocations allowed) ----------
__device__ float g_Q[BB * NN * CC];
__device__ float g_K[BB * NN * CC];
__device__ float g_V[BB * NN * CC];
__device__ float g_O[BB * NN * CC];

// =====================================================================
// Kernel 1: input projections.  out[b][n][co] = sum_ci W[co][ci]*X + bias
//   sel==0: Q from spatial_features [B,T,C,H,W]  (gather, t fixed per tile)
//   sel==1: K from temporal        [B,C,T,H,W] == [B,C,N]
//   sel==2: V from temporal
// Output stored row-major [B][N][C].
// grid (32, 4), 256 threads, dyn smem = 2*128*132*4 bytes
// =====================================================================
__global__ __launch_bounds__(256) void proj_in_kernel(
    const float* __restrict__ X, const float* __restrict__ W,
    const float* __restrict__ bias, int sel)
{
    extern __shared__ float sm[];
    float* Wsm = sm;               // [128][132]  Wsm[ci][co] (transposed)
    float* Xsm = sm + 128 * 132;   // [128][132]  Xsm[ci][j]
    const int b = blockIdx.y;
    const int n0 = blockIdx.x * 128;
    const int tid = threadIdx.x;

    // Load W transposed into smem
    for (int idx = tid; idx < 128 * 128; idx += 256) {
        int co = idx >> 7, ci = idx & 127;
        Wsm[ci * 132 + co] = W[idx];
    }
    // Load X tile (128 ci x 128 n), vectorized
    if (sel == 0) {
        int t = n0 >> 10, hw0 = n0 & 1023;
        const float* src = X + ((size_t)(b * TT + t) * CC) * HW + hw0;
        for (int idx = tid; idx < 128 * 32; idx += 256) {
            int ci = idx >> 5, c4 = (idx & 31) * 4;
            *(float4*)&Xsm[ci * 132 + c4] = *(const float4*)&src[ci * HW + c4];
        }
    } else {
        const float* src = X + (size_t)b * CC * NN + n0;
        for (int idx = tid; idx < 128 * 32; idx += 256) {
            int ci = idx >> 5, c4 = (idx & 31) * 4;
            *(float4*)&Xsm[ci * 132 + c4] = *(const float4*)&src[ci * NN + c4];
        }
    }
    __syncthreads();

    const int tx = tid & 15, ty = tid >> 4;  // co-block = ty*8, n-block = tx*8
    ull acc[8][4];
#pragma unroll
    for (int i = 0; i < 8; i++)
#pragma unroll
        for (int jp = 0; jp < 4; jp++) acc[i][jp] = 0ull;

#pragma unroll 4
    for (int ci = 0; ci < 128; ci++) {
        const float4 w0 = *(const float4*)&Wsm[ci * 132 + ty * 8];
        const float4 w1 = *(const float4*)&Wsm[ci * 132 + ty * 8 + 4];
        const ulonglong2 xa = *(const ulonglong2*)&Xsm[ci * 132 + tx * 8];
        const ulonglong2 xb = *(const ulonglong2*)&Xsm[ci * 132 + tx * 8 + 4];
        float wv[8];
        wv[0] = w0.x; wv[1] = w0.y; wv[2] = w0.z; wv[3] = w0.w;
        wv[4] = w1.x; wv[5] = w1.y; wv[6] = w1.z; wv[7] = w1.w;
#pragma unroll
        for (int i = 0; i < 8; i++) {
            ull wd = pack2(wv[i], wv[i]);
            acc[i][0] = fma2(xa.x, wd, acc[i][0]);
            acc[i][1] = fma2(xa.y, wd, acc[i][1]);
            acc[i][2] = fma2(xb.x, wd, acc[i][2]);
            acc[i][3] = fma2(xb.y, wd, acc[i][3]);
        }
    }

    float* out = (sel == 0) ? g_Q : (sel == 1) ? g_K : g_V;
    float a[8][8];
#pragma unroll
    for (int i = 0; i < 8; i++) {
        float bi = bias[ty * 8 + i];
#pragma unroll
        for (int jp = 0; jp < 4; jp++) {
            float lo, hi; unpack2(acc[i][jp], lo, hi);
            a[i][2 * jp] = lo + bi; a[i][2 * jp + 1] = hi + bi;
        }
    }
#pragma unroll
    for (int j = 0; j < 8; j++) {
        float* dst = out + ((size_t)b * NN + n0 + tx * 8 + j) * CC + ty * 8;
        *(float4*)dst       = make_float4(a[0][j], a[1][j], a[2][j], a[3][j]);
        *(float4*)(dst + 4) = make_float4(a[4][j], a[5][j], a[6][j], a[7][j]);
    }
}

// =====================================================================
// Kernel 2: flash attention (fp32, f32x2 packed FMA).
//   grid (64, 4), 256 threads. BM=64 queries, BK=64 keys per tile.
//   smem: Qs[64][132], Ks[128][68] (transposed), Vs[64][132], Ps[64][68]
// =====================================================================
__global__ __launch_bounds__(256) void attn_kernel()
{
    extern __shared__ float sm[];
    float* Qs = sm;                       // 64*132
    float* Ks = Qs + 64 * 132;            // 128*68  Ks[c][key]
    float* Vs = Ks + 128 * 68;            // 64*132  Vs[key][c]
    float* Ps = Vs + 64 * 132;            // 64*68   Ps[row][key]

    const int b = blockIdx.y;
    const int m0 = blockIdx.x * 64;
    const int tid = threadIdx.x;
    const int tx = tid & 15, ty = tid >> 4;   // rows = ty*4.., key-cols = tx*4.., out-cols = tx*8..

    const float* Qg = g_Q + ((size_t)b * NN + m0) * CC;
    const float* Kg = g_K + (size_t)b * NN * CC;
    const float* Vg = g_V + (size_t)b * NN * CC;

    // Load Q tile (vectorized)
    for (int idx = tid; idx < 64 * 32; idx += 256) {
        int r = idx >> 5, c4 = (idx & 31) * 4;
        *(float4*)&Qs[r * 132 + c4] = *(const float4*)&Qg[r * 128 + c4];
    }

    float m_run[4], l_run[4];
    ull o2[4][4];
#pragma unroll
    for (int i = 0; i < 4; i++) {
        m_run[i] = -1e30f; l_run[i] = 0.f;
#pragma unroll
        for (int jp = 0; jp < 4; jp++) o2[i][jp] = 0ull;
    }

    const float scale = 0.08838834764831843f;  // 1/sqrt(128)

    for (int kt = 0; kt < 64; kt++) {
        __syncthreads();  // protects Ks/Vs/Ps reuse and (first iter) Qs
        const float* Kt = Kg + (size_t)kt * 64 * CC;
        const float* Vt = Vg + (size_t)kt * 64 * CC;
        // K: load float4, store transposed (scalar); V: float4 straight through
        for (int idx = tid; idx < 64 * 32; idx += 256) {
            int r = idx >> 5, c4 = (idx & 31) * 4;
            float4 kv = *(const float4*)&Kt[r * 128 + c4];
            Ks[(c4 + 0) * 68 + r] = kv.x;
            Ks[(c4 + 1) * 68 + r] = kv.y;
            Ks[(c4 + 2) * 68 + r] = kv.z;
            Ks[(c4 + 3) * 68 + r] = kv.w;
            *(float4*)&Vs[r * 132 + c4] = *(const float4*)&Vt[r * 128 + c4];
        }
        __syncthreads();

        // ---- S = Q K^T  (per-thread 4 rows x 4 key-cols) ----
        ull s2[4][2];
#pragma unroll
        for (int i = 0; i < 4; i++) { s2[i][0] = 0ull; s2[i][1] = 0ull; }

#pragma unroll 2
        for (int c = 0; c < 128; c += 4) {
            float qr[4][4];
#pragma unroll
            for (int i = 0; i < 4; i++) {
                float4 q = *(const float4*)&Qs[(ty * 4 + i) * 132 + c];
                qr[i][0] = q.x; qr[i][1] = q.y; qr[i][2] = q.z; qr[i][3] = q.w;
            }
            ulonglong2 kp[4];
#pragma unroll
            for (int cc = 0; cc < 4; cc++)
                kp[cc] = *(const ulonglong2*)&Ks[(c + cc) * 68 + tx * 4];
#pragma unroll
            for (int cc = 0; cc < 4; cc++) {
#pragma unroll
                for (int i = 0; i < 4; i++) {
                    ull qd = pack2(qr[i][cc], qr[i][cc]);
                    s2[i][0] = fma2(kp[cc].x, qd, s2[i][0]);
                    s2[i][1] = fma2(kp[cc].y, qd, s2[i][1]);
                }
            }
        }

        // ---- online softmax ----
        float s[4][4];
#pragma unroll
        for (int i = 0; i < 4; i++) {
            float l0, h0, l1, h1;
            unpack2(s2[i][0], l0, h0); unpack2(s2[i][1], l1, h1);
            s[i][0] = l0 * scale; s[i][1] = h0 * scale;
            s[i][2] = l1 * scale; s[i][3] = h1 * scale;
        }
#pragma unroll
        for (int i = 0; i < 4; i++) {
            float mt = fmaxf(fmaxf(s[i][0], s[i][1]), fmaxf(s[i][2], s[i][3]));
#pragma unroll
            for (int off = 1; off < 16; off <<= 1)
                mt = fmaxf(mt, __shfl_xor_sync(0xffffffffu, mt, off));
            float mnew = fmaxf(m_run[i], mt);
            float alpha = __expf(m_run[i] - mnew);
            m_run[i] = mnew;
            float rs = 0.f;
#pragma unroll
            for (int j = 0; j < 4; j++) { float p = __expf(s[i][j] - mnew); s[i][j] = p; rs += p; }
#pragma unroll
            for (int off = 1; off < 16; off <<= 1)
                rs += __shfl_xor_sync(0xffffffffu, rs, off);
            l_run[i] = l_run[i] * alpha + rs;
            ull ad = pack2(alpha, alpha);
#pragma unroll
            for (int jp = 0; jp < 4; jp++) o2[i][jp] = mul2(o2[i][jp], ad);
            *(float4*)&Ps[(ty * 4 + i) * 68 + tx * 4] =
                make_float4(s[i][0], s[i][1], s[i][2], s[i][3]);
        }
        __syncthreads();

        // ---- O += P V  (per-thread 4 rows x 8 c-cols) ----
#pragma unroll 2
        for (int k = 0; k < 64; k++) {
            ulonglong2 va = *(const ulonglong2*)&Vs[k * 132 + tx * 8];
            ulonglong2 vb = *(const ulonglong2*)&Vs[k * 132 + tx * 8 + 4];
#pragma unroll
            for (int i = 0; i < 4; i++) {
                float p = Ps[(ty * 4 + i) * 68 + k];
                ull pd = pack2(p, p);
                o2[i][0] = fma2(va.x, pd, o2[i][0]);
                o2[i][1] = fma2(va.y, pd, o2[i][1]);
                o2[i][2] = fma2(vb.x, pd, o2[i][2]);
                o2[i][3] = fma2(vb.y, pd, o2[i][3]);
            }
        }
    }

    // epilogue: O /= l, store [B][N][C]
#pragma unroll
    for (int i = 0; i < 4; i++) {
        float inv = 1.0f / l_run[i];
        float o[8];
#pragma unroll
        for (int jp = 0; jp < 4; jp++) unpack2(o2[i][jp], o[2 * jp], o[2 * jp + 1]);
        float* dst = g_O + ((size_t)b * NN + m0 + ty * 4 + i) * CC + tx * 8;
        *(float4*)dst       = make_float4(o[0] * inv, o[1] * inv, o[2] * inv, o[3] * inv);
        *(float4*)(dst + 4) = make_float4(o[4] * inv, o[5] * inv, o[6] * inv, o[7] * inv);
    }
}

// =====================================================================
// Kernel 3: output projection. out[b][co][n] = sum_c Wo[co][c]*O[b][n][c] + bo
// grid (32, 4), 256 threads, dyn smem = 2*128*132*4
// =====================================================================
__global__ __launch_bounds__(256) void proj_out_kernel(
    const float* __restrict__ W, const float* __restrict__ bias,
    float* __restrict__ out)
{
    extern __shared__ float sm[];
    float* Wsm = sm;               // [128][132]  Wsm[c][co]
    float* Xsm = sm + 128 * 132;   // [128][132]  Xsm[c][n]
    const int b = blockIdx.y;
    const int n0 = blockIdx.x * 128;
    const int tid = threadIdx.x;

    for (int idx = tid; idx < 128 * 128; idx += 256) {
        int co = idx >> 7, c = idx & 127;
        Wsm[c * 132 + co] = W[idx];
    }
    const float* src = g_O + ((size_t)b * NN + n0) * CC;
    for (int idx = tid; idx < 128 * 32; idx += 256) {
        int n = idx >> 5, c4 = (idx & 31) * 4;
        float4 v = *(const float4*)&src[n * CC + c4];
        Xsm[(c4 + 0) * 132 + n] = v.x;
        Xsm[(c4 + 1) * 132 + n] = v.y;
        Xsm[(c4 + 2) * 132 + n] = v.z;
        Xsm[(c4 + 3) * 132 + n] = v.w;
    }
    __syncthreads();

    const int tx = tid & 15, ty = tid >> 4;
    ull acc[8][4];
#pragma unroll
    for (int i = 0; i < 8; i++)
#pragma unroll
        for (int jp = 0; jp < 4; jp++) acc[i][jp] = 0ull;

#pragma unroll 4
    for (int c = 0; c < 128; c++) {
        const float4 w0 = *(const float4*)&Wsm[c * 132 + ty * 8];
        const float4 w1 = *(const float4*)&Wsm[c * 132 + ty * 8 + 4];
        const ulonglong2 xa = *(const ulonglong2*)&Xsm[c * 132 + tx * 8];
        const ulonglong2 xb = *(const ulonglong2*)&Xsm[c * 132 + tx * 8 + 4];
        float wv[8];
        wv[0] = w0.x; wv[1] = w0.y; wv[2] = w0.z; wv[3] = w0.w;
        wv[4] = w1.x; wv[5] = w1.y; wv[6] = w1.z; wv[7] = w1.w;
#pragma unroll
        for (int i = 0; i < 8; i++) {
            ull wd = pack2(wv[i], wv[i]);
            acc[i][0] = fma2(xa.x, wd, acc[i][0]);
            acc[i][1] = fma2(xa.y, wd, acc[i][1]);
            acc[i][2] = fma2(xb.x, wd, acc[i][2]);
            acc[i][3] = fma2(xb.y, wd, acc[i][3]);
        }
    }

    float a[8][8];
#pragma unroll
    for (int i = 0; i < 8; i++) {
        float bi = bias[ty * 8 + i];
#pragma unroll
        for (int jp = 0; jp < 4; jp++) {
            float lo, hi; unpack2(acc[i][jp], lo, hi);
            a[i][2 * jp] = lo + bi; a[i][2 * jp + 1] = hi + bi;
        }
    }
#pragma unroll
    for (int i = 0; i < 8; i++) {
        float* dst = out + ((size_t)b * CC + ty * 8 + i) * NN + n0 + tx * 8;
        *(float4*)dst       = make_float4(a[i][0], a[i][1], a[i][2], a[i][3]);
        *(float4*)(dst + 4) = make_float4(a[i][4], a[i][5], a[i][6], a[i][7]);
    }
}

// =====================================================================
extern "C" void kernel_launch(void* const* d_in, const int* in_sizes, int n_in,
                              void* d_out, int out_size)
{
    const float* spatial  = (const float*)d_in[0];
    const float* temporal = (const float*)d_in[1];
    const float* Wq = (const float*)d_in[2];
    const float* bq = (const float*)d_in[3];
    const float* Wk = (const float*)d_in[4];
    const float* bk = (const float*)d_in[5];
    const float* Wv = (const float*)d_in[6];
    const float* bv = (const float*)d_in[7];
    const float* Wo = (const float*)d_in[8];
    const float* bo = (const float*)d_in[9];
    float* out = (float*)d_out;

    const int smem_proj = 2 * 128 * 132 * 4;                            // 135168
    const int smem_attn = (64 * 132 + 128 * 68 + 64 * 132 + 64 * 68) * 4; // 119808

    cudaFuncSetAttribute(proj_in_kernel,  cudaFuncAttributeMaxDynamicSharedMemorySize, smem_proj);
    cudaFuncSetAttribute(proj_out_kernel, cudaFuncAttributeMaxDynamicSharedMemorySize, smem_proj);
    cudaFuncSetAttribute(attn_kernel,     cudaFuncAttributeMaxDynamicSharedMemorySize, smem_attn);

    dim3 gp(32, 4);
    proj_in_kernel<<<gp, 256, smem_proj>>>(spatial,  Wq, bq, 0);
    proj_in_kernel<<<gp, 256, smem_proj>>>(temporal, Wk, bk, 1);
    proj_in_kernel<<<gp, 256, smem_proj>>>(temporal, Wv, bv, 2);
    attn_kernel<<<dim3(64, 4), 256, smem_attn>>>();
    proj_out_kernel<<<gp, 256, smem_proj>>>(Wo, bo, out);
}